// round 4
// baseline (speedup 1.0000x reference)
#include <cuda_runtime.h>
#include <cstdint>

// ---------------------------------------------------------------------------
// LSTM decoder, restructured:
//   Xproj[t,b,:] = x_t @ kernel[0:256,:]              (parallel pre-GEMM)
//   R_eff  = rec_kernel + dense_w @ kernel[256:320,:] (feedback folded in)
//   z_t    = Xproj[t] + bias_eff + h_{t-1} @ R_eff    (persistent kernel, 1 sync/step)
//   y_t    = h_t @ dense_w + dense_b
// R2: 512 threads, smem-staged h via cp.async.cg (double-buffered), xproj
//     prefetched at step start.
// ---------------------------------------------------------------------------

#define B_    128
#define T_    512
#define D_    256
#define U_    512
#define G4_   2048
#define OUT_  64
#define NTH   512
#define KC_   32          // k-chunk staged per cp.async round
#define NCH   (U_ / KC_)  // 16 chunks

typedef unsigned long long ull;

// ------------------------- device scratch (static, no allocs) --------------
__device__ float g_xproj[(size_t)T_ * G4_ * B_];   // [t][col][b]
__device__ float g_ReffP[U_ * G4_];                // permuted per-block [blk][k][c]
__device__ float g_beP[G4_];
__device__ float g_brawP[G4_];
__device__ float g_hTA[U_ * B_];                   // h transposed [k][b]
__device__ float g_hTB[U_ * B_];
__device__ float g_hrA[B_ * U_];                   // h row-major [b][u]
__device__ float g_hrB[B_ * U_];
__device__ unsigned g_cnt = 0;
__device__ unsigned g_gen = 0;

// ------------------------- small helpers -----------------------------------
__device__ __forceinline__ void fma2(ull &acc, ull a, ull b) {
    asm("fma.rn.f32x2 %0, %1, %2, %0;" : "+l"(acc) : "l"(a), "l"(b));
}
__device__ __forceinline__ ull pack2(float x, float y) {
    ull r; asm("mov.b64 %0, {%1, %2};" : "=l"(r) : "f"(x), "f"(y)); return r;
}
__device__ __forceinline__ float2 unpack2(ull v) {
    float2 r; asm("mov.b64 {%0, %1}, %2;" : "=f"(r.x), "=f"(r.y) : "l"(v)); return r;
}
__device__ __forceinline__ float sigm(float x) {
    return __fdividef(1.f, 1.f + __expf(-x));
}
__device__ __forceinline__ float tanh_(float x) {
    float a = fabsf(x);
    float e = __expf(-2.f * a);
    float r = __fdividef(1.f - e, 1.f + e);
    return copysignf(r, x);
}
__device__ __forceinline__ void cpasync16(uint32_t saddr, const float *g) {
    asm volatile("cp.async.cg.shared.global [%0], [%1], 16;"
                 :: "r"(saddr), "l"(g));
}
__device__ __forceinline__ void cpcommit() {
    asm volatile("cp.async.commit_group;");
}
__device__ __forceinline__ void cpwait0() {
    asm volatile("cp.async.wait_group 0;");
}

// spin grid barrier (all CTAs co-resident: 128 blocks, 1/SM by smem)
__device__ __forceinline__ void grid_sync() {
    __syncthreads();
    if (threadIdx.x == 0) {
        unsigned gen = *((volatile unsigned *)&g_gen);
        __threadfence();
        unsigned prev = atomicAdd(&g_cnt, 1u);
        if (prev == gridDim.x - 1) {
            atomicExch(&g_cnt, 0u);
            __threadfence();
            atomicAdd(&g_gen, 1u);
        } else {
            while (*((volatile unsigned *)&g_gen) == gen) { }
        }
        __threadfence();
    }
    __syncthreads();
}

// ------------------------- prep: R_eff, bias_eff ----------------------------
__global__ void prep_reff_kernel(const float *__restrict__ wk,
                                 const float *__restrict__ rec,
                                 const float *__restrict__ dw) {
    int k = blockIdx.x;
    int tid = threadIdx.x;
    __shared__ float dws[OUT_];
    if (tid < OUT_) dws[tid] = dw[k * OUT_ + tid];
    __syncthreads();
    for (int col = tid; col < G4_; col += 256) {
        float acc = rec[k * G4_ + col];
#pragma unroll 16
        for (int j = 0; j < OUT_; j++)
            acc += dws[j] * wk[(size_t)(D_ + j) * G4_ + col];
        int u = col & (U_ - 1), gate = col >> 9;
        g_ReffP[(size_t)(u >> 2) * (U_ * 16) + k * 16 + (u & 3) * 4 + gate] = acc;
    }
}

__global__ void prep_bias_kernel(const float *__restrict__ wk,
                                 const float *__restrict__ bias,
                                 const float *__restrict__ db) {
    int col = blockIdx.x * 256 + threadIdx.x;
    float acc = 0.f;
#pragma unroll 16
    for (int j = 0; j < OUT_; j++)
        acc += db[j] * wk[(size_t)(D_ + j) * G4_ + col];
    int u = col & (U_ - 1), gate = col >> 9;
    int idx = (u >> 2) * 16 + (u & 3) * 4 + gate;
    g_brawP[idx] = bias[col];
    g_beP[idx] = bias[col] + acc;
}

// ------------------------- Xproj GEMM ---------------------------------------
#define XKC 16
__global__ void __launch_bounds__(256) xproj_kernel(const float *__restrict__ inp,
                                                    const float *__restrict__ wk) {
    __shared__ float sK[XKC][132];
    __shared__ float sX[XKC][136];
    int tid = threadIdx.x;
    int col0 = blockIdx.x * 128;
    int t = blockIdx.y;
    int tc = tid & 15, tb = tid >> 4;
    int c0 = tc * 8, b0 = tb * 8;

    ull acc[8][4];
#pragma unroll
    for (int c = 0; c < 8; c++)
#pragma unroll
        for (int j = 0; j < 4; j++) acc[c][j] = 0ULL;

    for (int d0 = 0; d0 < D_; d0 += XKC) {
        __syncthreads();
        {
            int l = tid * 8;
            int dd = l >> 7, cc = l & 127;
            const float *src = wk + (size_t)(d0 + dd) * G4_ + col0 + cc;
            *(float4 *)&sK[dd][cc] = *(const float4 *)src;
            *(float4 *)&sK[dd][cc + 4] = *(const float4 *)(src + 4);
        }
        {
            int bb = tid >> 1, f4 = tid & 1;
            const float *src = inp + (size_t)bb * (T_ * D_) + (size_t)t * D_ + d0 + f4 * 8;
            float4 v0 = *(const float4 *)src;
            float4 v1 = *(const float4 *)(src + 4);
            int dbase = f4 * 8;
            sX[dbase + 0][bb] = v0.x; sX[dbase + 1][bb] = v0.y;
            sX[dbase + 2][bb] = v0.z; sX[dbase + 3][bb] = v0.w;
            sX[dbase + 4][bb] = v1.x; sX[dbase + 5][bb] = v1.y;
            sX[dbase + 6][bb] = v1.z; sX[dbase + 7][bb] = v1.w;
        }
        __syncthreads();
#pragma unroll
        for (int dd = 0; dd < XKC; dd++) {
            float4 a0 = *(float4 *)&sK[dd][c0];
            float4 a1 = *(float4 *)&sK[dd][c0 + 4];
            const ull *bp = (const ull *)&sX[dd][b0];
            ull bv0 = bp[0], bv1 = bp[1], bv2 = bp[2], bv3 = bp[3];
            float av[8] = {a0.x, a0.y, a0.z, a0.w, a1.x, a1.y, a1.z, a1.w};
#pragma unroll
            for (int c = 0; c < 8; c++) {
                ull ap = pack2(av[c], av[c]);
                fma2(acc[c][0], ap, bv0);
                fma2(acc[c][1], ap, bv1);
                fma2(acc[c][2], ap, bv2);
                fma2(acc[c][3], ap, bv3);
            }
        }
    }
#pragma unroll
    for (int c = 0; c < 8; c++) {
        size_t base = ((size_t)t * G4_ + col0 + c0 + c) * B_ + b0;
#pragma unroll
        for (int j = 0; j < 4; j++)
            *(ull *)&g_xproj[base + 2 * j] = acc[c][j];
    }
}

// ------------------------- persistent recurrence ----------------------------
struct SmemP {
    float Rs[U_ * 16];        // 32 KB   (16B aligned: first member)
    float dw[U_ * OUT_];      // 128 KB
    float hbuf[2][KC_ * B_];  // 2 x 16 KB
    float red[3 * 16 * B_];   // 24 KB  [q-1][c][b]
    float cst[4 * B_];        // 2 KB
    float hst[U_];            // 2 KB
    float ypart[NTH];         // 2 KB
    float be[16];
    float be0[16];
    float db[OUT_];
};

__global__ void __launch_bounds__(NTH, 1) lstm_persist(const float *__restrict__ dense_w,
                                                       const float *__restrict__ dense_b,
                                                       float *__restrict__ out) {
    extern __shared__ char smraw[];
    SmemP *sm = (SmemP *)smraw;
    int tid = threadIdx.x;
    int bid = blockIdx.x;
    int u0 = bid * 4;
    int b = tid & (B_ - 1);
    int q = tid >> 7;                 // k-interleave lane, 0..3

    // one-time smem loads
    for (int i = tid * 4; i < U_ * OUT_; i += NTH * 4)
        *(float4 *)&sm->dw[i] = *(const float4 *)&dense_w[i];
    for (int i = tid * 4; i < U_ * 16; i += NTH * 4)
        *(float4 *)&sm->Rs[i] = *(const float4 *)&g_ReffP[(size_t)bid * (U_ * 16) + i];
    if (tid < OUT_) sm->db[tid] = dense_b[tid];
    if (tid < 16) {
        sm->be[tid] = g_beP[bid * 16 + tid];
        sm->be0[tid] = g_brawP[bid * 16 + tid];
    }
    for (int i = tid; i < 4 * B_; i += NTH) sm->cst[i] = 0.f;
    __syncthreads();

    uint32_t hb_s[2];
    hb_s[0] = (uint32_t)__cvta_generic_to_shared(sm->hbuf[0]);
    hb_s[1] = (uint32_t)__cvta_generic_to_shared(sm->hbuf[1]);

    int p = 0;
    for (int t = 0; t < T_; t++) {
        const float *hrd = (p == 0) ? g_hTA : g_hTB;
        float *hwr = (p == 0) ? g_hTB : g_hTA;
        float *hrow = (p == 0) ? g_hrB : g_hrA;

        // prefetch xproj (DRAM) early — hidden under the GEMM
        float xpf[16];
        size_t base_t = (size_t)t * G4_ * B_;
        if (q == 0) {
#pragma unroll
            for (int c = 0; c < 16; c++) {
                int col = ((c & 3) << 9) + u0 + (c >> 2);
                xpf[c] = __ldcg(&g_xproj[base_t + (size_t)col * B_ + b]);
            }
        }

        ull acc[8];
#pragma unroll
        for (int i = 0; i < 8; i++) acc[i] = 0ULL;

        if (t) {
            // stage chunk 0
            cpasync16(hb_s[0] + tid * 16, hrd + tid * 4);
            cpasync16(hb_s[0] + (tid + NTH) * 16, hrd + (tid + NTH) * 4);
            cpcommit();

            for (int ch = 0; ch < NCH; ch++) {
                int cur = ch & 1;
                cpwait0();
                __syncthreads();
                if (ch + 1 < NCH) {
                    int nxt = cur ^ 1;
                    const float *src = hrd + (ch + 1) * (KC_ * B_);
                    cpasync16(hb_s[nxt] + tid * 16, src + tid * 4);
                    cpasync16(hb_s[nxt] + (tid + NTH) * 16, src + (tid + NTH) * 4);
                    cpcommit();
                }
                const float *hb = sm->hbuf[cur];
                int kgbase = ch * KC_ + q;
#pragma unroll
                for (int i = 0; i < 8; i++) {
                    int kl = 4 * i + q;
                    float hv = hb[kl * B_ + b];
                    ull hh = pack2(hv, hv);
                    const ulonglong2 *R2 =
                        (const ulonglong2 *)(sm->Rs + (size_t)(kgbase + 4 * i) * 16);
                    ulonglong2 r0 = R2[0], r1 = R2[1], r2 = R2[2], r3 = R2[3];
                    fma2(acc[0], hh, r0.x); fma2(acc[1], hh, r0.y);
                    fma2(acc[2], hh, r1.x); fma2(acc[3], hh, r1.y);
                    fma2(acc[4], hh, r2.x); fma2(acc[5], hh, r2.y);
                    fma2(acc[6], hh, r3.x); fma2(acc[7], hh, r3.y);
                }
            }
        }

        // reduce 4 k-partials
        if (q) {
            float *rd = sm->red + (q - 1) * (16 * B_);
#pragma unroll
            for (int i = 0; i < 8; i++) {
                float2 v = unpack2(acc[i]);
                rd[(2 * i) * B_ + b] = v.x;
                rd[(2 * i + 1) * B_ + b] = v.y;
            }
        }
        __syncthreads();

        if (q == 0) {
            float z[16];
#pragma unroll
            for (int i = 0; i < 8; i++) {
                float2 v = unpack2(acc[i]);
                z[2 * i] = v.x;
                z[2 * i + 1] = v.y;
            }
#pragma unroll
            for (int j = 0; j < 3; j++) {
                const float *rd = sm->red + j * (16 * B_);
#pragma unroll
                for (int c = 0; c < 16; c++) z[c] += rd[c * B_ + b];
            }
#pragma unroll
            for (int c = 0; c < 16; c++)
                z[c] += xpf[c] + ((t == 0) ? sm->be0[c] : sm->be[c]);

            float hna[4];
#pragma unroll
            for (int ul = 0; ul < 4; ul++) {
                float zi = z[ul * 4 + 0], zf = z[ul * 4 + 1];
                float zg = z[ul * 4 + 2], zo = z[ul * 4 + 3];
                float ig = sigm(zi), fg = sigm(zf);
                float gg = tanh_(zg), og = sigm(zo);
                float cold = sm->cst[ul * B_ + b];
                float cn = fg * cold + ig * gg;
                sm->cst[ul * B_ + b] = cn;
                float hv = og * tanh_(cn);
                hna[ul] = hv;
                hwr[(u0 + ul) * B_ + b] = hv;
            }
            *(float4 *)&hrow[(size_t)b * U_ + u0] =
                make_float4(hna[0], hna[1], hna[2], hna[3]);
        }
        __threadfence();
        grid_sync();

        // ---- dense head: block bid computes y[bid, :] for this t ----
        sm->hst[tid] = __ldcg(&hrow[(size_t)bid * U_ + tid]);
        __syncthreads();
        {
            int o = tid & (OUT_ - 1), q8 = tid >> 6;   // 8 u-groups of 64
            const float *hq = sm->hst + q8 * 64;
            const float *dwq = sm->dw + (size_t)q8 * 64 * OUT_ + o;
            float a0 = 0.f, a1 = 0.f, a2 = 0.f, a3 = 0.f;
#pragma unroll
            for (int u = 0; u < 64; u += 4) {
                a0 = fmaf(hq[u + 0], dwq[(u + 0) * OUT_], a0);
                a1 = fmaf(hq[u + 1], dwq[(u + 1) * OUT_], a1);
                a2 = fmaf(hq[u + 2], dwq[(u + 2) * OUT_], a2);
                a3 = fmaf(hq[u + 3], dwq[(u + 3) * OUT_], a3);
            }
            sm->ypart[tid] = a0 + a1 + a2 + a3;
        }
        __syncthreads();
        if (tid < OUT_) {
            float y = sm->db[tid];
#pragma unroll
            for (int j = 0; j < 8; j++) y += sm->ypart[j * 64 + tid];
            out[((size_t)bid * T_ + t) * OUT_ + tid] = y;
        }
        p ^= 1;
    }
}

// ------------------------- launch ------------------------------------------
extern "C" void kernel_launch(void *const *d_in, const int *in_sizes, int n_in,
                              void *d_out, int out_size) {
    const float *inputs  = (const float *)d_in[0];   // [128,512,256]
    const float *kernelw = (const float *)d_in[1];   // [320,2048]
    const float *rec     = (const float *)d_in[2];   // [512,2048]
    const float *bias    = (const float *)d_in[3];   // [2048]
    const float *dense_w = (const float *)d_in[4];   // [512,64]
    const float *dense_b = (const float *)d_in[5];   // [64]
    float *out = (float *)d_out;                     // [128,512,64]

    (void)in_sizes; (void)n_in; (void)out_size;

    cudaFuncSetAttribute(lstm_persist,
                         cudaFuncAttributeMaxDynamicSharedMemorySize,
                         (int)sizeof(SmemP));

    prep_reff_kernel<<<U_, 256>>>(kernelw, rec, dense_w);
    prep_bias_kernel<<<G4_ / 256, 256>>>(kernelw, bias, dense_b);
    xproj_kernel<<<dim3(G4_ / 128, T_), 256>>>(inputs, kernelw);
    lstm_persist<<<B_, 512, (int)sizeof(SmemP)>>>(dense_w, dense_b, out);
}

// round 5
// speedup vs baseline: 1.0532x; 1.0532x over previous
#include <cuda_runtime.h>
#include <cstdint>

// ---------------------------------------------------------------------------
// LSTM decoder, restructured:
//   Xproj[t,b,:] = x_t @ kernel[0:256,:]              (parallel pre-GEMM)
//   R_eff  = rec_kernel + dense_w @ kernel[256:320,:] (feedback folded in)
//   z_t    = Xproj[t] + bias_eff + h_{t-1} @ R_eff    (persistent kernel, 1 sync/step)
//   y_t    = h_t @ dense_w + dense_b
// R2: 512 threads, smem-staged h via cp.async.cg (double-buffered), xproj
//     prefetched at step start.
// ---------------------------------------------------------------------------

#define B_    128
#define T_    512
#define D_    256
#define U_    512
#define G4_   2048
#define OUT_  64
#define NTH   512
#define KC_   32          // k-chunk staged per cp.async round
#define NCH   (U_ / KC_)  // 16 chunks

typedef unsigned long long ull;

// ------------------------- device scratch (static, no allocs) --------------
__device__ float g_xproj[(size_t)T_ * G4_ * B_];   // [t][col][b]
__device__ float g_ReffP[U_ * G4_];                // permuted per-block [blk][k][c]
__device__ float g_beP[G4_];
__device__ float g_brawP[G4_];
__device__ float g_hTA[U_ * B_];                   // h transposed [k][b]
__device__ float g_hTB[U_ * B_];
__device__ float g_hrA[B_ * U_];                   // h row-major [b][u]
__device__ float g_hrB[B_ * U_];
__device__ unsigned g_cnt = 0;
__device__ unsigned g_gen = 0;

// ------------------------- small helpers -----------------------------------
__device__ __forceinline__ void fma2(ull &acc, ull a, ull b) {
    asm("fma.rn.f32x2 %0, %1, %2, %0;" : "+l"(acc) : "l"(a), "l"(b));
}
__device__ __forceinline__ ull pack2(float x, float y) {
    ull r; asm("mov.b64 %0, {%1, %2};" : "=l"(r) : "f"(x), "f"(y)); return r;
}
__device__ __forceinline__ float2 unpack2(ull v) {
    float2 r; asm("mov.b64 {%0, %1}, %2;" : "=f"(r.x), "=f"(r.y) : "l"(v)); return r;
}
__device__ __forceinline__ float sigm(float x) {
    return __fdividef(1.f, 1.f + __expf(-x));
}
__device__ __forceinline__ float tanh_(float x) {
    float a = fabsf(x);
    float e = __expf(-2.f * a);
    float r = __fdividef(1.f - e, 1.f + e);
    return copysignf(r, x);
}
__device__ __forceinline__ void cpasync16(uint32_t saddr, const float *g) {
    asm volatile("cp.async.cg.shared.global [%0], [%1], 16;"
                 :: "r"(saddr), "l"(g));
}
__device__ __forceinline__ void cpcommit() {
    asm volatile("cp.async.commit_group;");
}
__device__ __forceinline__ void cpwait0() {
    asm volatile("cp.async.wait_group 0;");
}

// spin grid barrier (all CTAs co-resident: 128 blocks, 1/SM by smem)
__device__ __forceinline__ void grid_sync() {
    __syncthreads();
    if (threadIdx.x == 0) {
        unsigned gen = *((volatile unsigned *)&g_gen);
        __threadfence();
        unsigned prev = atomicAdd(&g_cnt, 1u);
        if (prev == gridDim.x - 1) {
            atomicExch(&g_cnt, 0u);
            __threadfence();
            atomicAdd(&g_gen, 1u);
        } else {
            while (*((volatile unsigned *)&g_gen) == gen) { }
        }
        __threadfence();
    }
    __syncthreads();
}

// ------------------------- prep: R_eff, bias_eff ----------------------------
__global__ void prep_reff_kernel(const float *__restrict__ wk,
                                 const float *__restrict__ rec,
                                 const float *__restrict__ dw) {
    int k = blockIdx.x;
    int tid = threadIdx.x;
    __shared__ float dws[OUT_];
    if (tid < OUT_) dws[tid] = dw[k * OUT_ + tid];
    __syncthreads();
    for (int col = tid; col < G4_; col += 256) {
        float acc = rec[k * G4_ + col];
#pragma unroll 16
        for (int j = 0; j < OUT_; j++)
            acc += dws[j] * wk[(size_t)(D_ + j) * G4_ + col];
        int u = col & (U_ - 1), gate = col >> 9;
        g_ReffP[(size_t)(u >> 2) * (U_ * 16) + k * 16 + (u & 3) * 4 + gate] = acc;
    }
}

__global__ void prep_bias_kernel(const float *__restrict__ wk,
                                 const float *__restrict__ bias,
                                 const float *__restrict__ db) {
    int col = blockIdx.x * 256 + threadIdx.x;
    float acc = 0.f;
#pragma unroll 16
    for (int j = 0; j < OUT_; j++)
        acc += db[j] * wk[(size_t)(D_ + j) * G4_ + col];
    int u = col & (U_ - 1), gate = col >> 9;
    int idx = (u >> 2) * 16 + (u & 3) * 4 + gate;
    g_brawP[idx] = bias[col];
    g_beP[idx] = bias[col] + acc;
}

// ------------------------- Xproj GEMM ---------------------------------------
#define XKC 16
__global__ void __launch_bounds__(256) xproj_kernel(const float *__restrict__ inp,
                                                    const float *__restrict__ wk) {
    __shared__ float sK[XKC][132];
    __shared__ float sX[XKC][136];
    int tid = threadIdx.x;
    int col0 = blockIdx.x * 128;
    int t = blockIdx.y;
    int tc = tid & 15, tb = tid >> 4;
    int c0 = tc * 8, b0 = tb * 8;

    ull acc[8][4];
#pragma unroll
    for (int c = 0; c < 8; c++)
#pragma unroll
        for (int j = 0; j < 4; j++) acc[c][j] = 0ULL;

    for (int d0 = 0; d0 < D_; d0 += XKC) {
        __syncthreads();
        {
            int l = tid * 8;
            int dd = l >> 7, cc = l & 127;
            const float *src = wk + (size_t)(d0 + dd) * G4_ + col0 + cc;
            *(float4 *)&sK[dd][cc] = *(const float4 *)src;
            *(float4 *)&sK[dd][cc + 4] = *(const float4 *)(src + 4);
        }
        {
            int bb = tid >> 1, f4 = tid & 1;
            const float *src = inp + (size_t)bb * (T_ * D_) + (size_t)t * D_ + d0 + f4 * 8;
            float4 v0 = *(const float4 *)src;
            float4 v1 = *(const float4 *)(src + 4);
            int dbase = f4 * 8;
            sX[dbase + 0][bb] = v0.x; sX[dbase + 1][bb] = v0.y;
            sX[dbase + 2][bb] = v0.z; sX[dbase + 3][bb] = v0.w;
            sX[dbase + 4][bb] = v1.x; sX[dbase + 5][bb] = v1.y;
            sX[dbase + 6][bb] = v1.z; sX[dbase + 7][bb] = v1.w;
        }
        __syncthreads();
#pragma unroll
        for (int dd = 0; dd < XKC; dd++) {
            float4 a0 = *(float4 *)&sK[dd][c0];
            float4 a1 = *(float4 *)&sK[dd][c0 + 4];
            const ull *bp = (const ull *)&sX[dd][b0];
            ull bv0 = bp[0], bv1 = bp[1], bv2 = bp[2], bv3 = bp[3];
            float av[8] = {a0.x, a0.y, a0.z, a0.w, a1.x, a1.y, a1.z, a1.w};
#pragma unroll
            for (int c = 0; c < 8; c++) {
                ull ap = pack2(av[c], av[c]);
                fma2(acc[c][0], ap, bv0);
                fma2(acc[c][1], ap, bv1);
                fma2(acc[c][2], ap, bv2);
                fma2(acc[c][3], ap, bv3);
            }
        }
    }
#pragma unroll
    for (int c = 0; c < 8; c++) {
        size_t base = ((size_t)t * G4_ + col0 + c0 + c) * B_ + b0;
#pragma unroll
        for (int j = 0; j < 4; j++)
            *(ull *)&g_xproj[base + 2 * j] = acc[c][j];
    }
}

// ------------------------- persistent recurrence ----------------------------
struct SmemP {
    float Rs[U_ * 16];        // 32 KB   (16B aligned: first member)
    float dw[U_ * OUT_];      // 128 KB
    float hbuf[2][KC_ * B_];  // 2 x 16 KB
    float red[3 * 16 * B_];   // 24 KB  [q-1][c][b]
    float cst[4 * B_];        // 2 KB
    float hst[U_];            // 2 KB
    float ypart[NTH];         // 2 KB
    float be[16];
    float be0[16];
    float db[OUT_];
};

__global__ void __launch_bounds__(NTH, 1) lstm_persist(const float *__restrict__ dense_w,
                                                       const float *__restrict__ dense_b,
                                                       float *__restrict__ out) {
    extern __shared__ char smraw[];
    SmemP *sm = (SmemP *)smraw;
    int tid = threadIdx.x;
    int bid = blockIdx.x;
    int u0 = bid * 4;
    int b = tid & (B_ - 1);
    int q = tid >> 7;                 // k-interleave lane, 0..3

    // one-time smem loads
    for (int i = tid * 4; i < U_ * OUT_; i += NTH * 4)
        *(float4 *)&sm->dw[i] = *(const float4 *)&dense_w[i];
    for (int i = tid * 4; i < U_ * 16; i += NTH * 4)
        *(float4 *)&sm->Rs[i] = *(const float4 *)&g_ReffP[(size_t)bid * (U_ * 16) + i];
    if (tid < OUT_) sm->db[tid] = dense_b[tid];
    if (tid < 16) {
        sm->be[tid] = g_beP[bid * 16 + tid];
        sm->be0[tid] = g_brawP[bid * 16 + tid];
    }
    for (int i = tid; i < 4 * B_; i += NTH) sm->cst[i] = 0.f;
    __syncthreads();

    uint32_t hb_s[2];
    hb_s[0] = (uint32_t)__cvta_generic_to_shared(sm->hbuf[0]);
    hb_s[1] = (uint32_t)__cvta_generic_to_shared(sm->hbuf[1]);

    int p = 0;
    for (int t = 0; t < T_; t++) {
        const float *hrd = (p == 0) ? g_hTA : g_hTB;
        float *hwr = (p == 0) ? g_hTB : g_hTA;
        float *hrow = (p == 0) ? g_hrB : g_hrA;

        // prefetch xproj (DRAM) early — hidden under the GEMM
        float xpf[16];
        size_t base_t = (size_t)t * G4_ * B_;
        if (q == 0) {
#pragma unroll
            for (int c = 0; c < 16; c++) {
                int col = ((c & 3) << 9) + u0 + (c >> 2);
                xpf[c] = __ldcg(&g_xproj[base_t + (size_t)col * B_ + b]);
            }
        }

        ull acc[8];
#pragma unroll
        for (int i = 0; i < 8; i++) acc[i] = 0ULL;

        if (t) {
            // stage chunk 0
            cpasync16(hb_s[0] + tid * 16, hrd + tid * 4);
            cpasync16(hb_s[0] + (tid + NTH) * 16, hrd + (tid + NTH) * 4);
            cpcommit();

            for (int ch = 0; ch < NCH; ch++) {
                int cur = ch & 1;
                cpwait0();
                __syncthreads();
                if (ch + 1 < NCH) {
                    int nxt = cur ^ 1;
                    const float *src = hrd + (ch + 1) * (KC_ * B_);
                    cpasync16(hb_s[nxt] + tid * 16, src + tid * 4);
                    cpasync16(hb_s[nxt] + (tid + NTH) * 16, src + (tid + NTH) * 4);
                    cpcommit();
                }
                const float *hb = sm->hbuf[cur];
                int kgbase = ch * KC_ + q;
#pragma unroll
                for (int i = 0; i < 8; i++) {
                    int kl = 4 * i + q;
                    float hv = hb[kl * B_ + b];
                    ull hh = pack2(hv, hv);
                    const ulonglong2 *R2 =
                        (const ulonglong2 *)(sm->Rs + (size_t)(kgbase + 4 * i) * 16);
                    ulonglong2 r0 = R2[0], r1 = R2[1], r2 = R2[2], r3 = R2[3];
                    fma2(acc[0], hh, r0.x); fma2(acc[1], hh, r0.y);
                    fma2(acc[2], hh, r1.x); fma2(acc[3], hh, r1.y);
                    fma2(acc[4], hh, r2.x); fma2(acc[5], hh, r2.y);
                    fma2(acc[6], hh, r3.x); fma2(acc[7], hh, r3.y);
                }
            }
        }

        // reduce 4 k-partials
        if (q) {
            float *rd = sm->red + (q - 1) * (16 * B_);
#pragma unroll
            for (int i = 0; i < 8; i++) {
                float2 v = unpack2(acc[i]);
                rd[(2 * i) * B_ + b] = v.x;
                rd[(2 * i + 1) * B_ + b] = v.y;
            }
        }
        __syncthreads();

        if (q == 0) {
            float z[16];
#pragma unroll
            for (int i = 0; i < 8; i++) {
                float2 v = unpack2(acc[i]);
                z[2 * i] = v.x;
                z[2 * i + 1] = v.y;
            }
#pragma unroll
            for (int j = 0; j < 3; j++) {
                const float *rd = sm->red + j * (16 * B_);
#pragma unroll
                for (int c = 0; c < 16; c++) z[c] += rd[c * B_ + b];
            }
#pragma unroll
            for (int c = 0; c < 16; c++)
                z[c] += xpf[c] + ((t == 0) ? sm->be0[c] : sm->be[c]);

            float hna[4];
#pragma unroll
            for (int ul = 0; ul < 4; ul++) {
                float zi = z[ul * 4 + 0], zf = z[ul * 4 + 1];
                float zg = z[ul * 4 + 2], zo = z[ul * 4 + 3];
                float ig = sigm(zi), fg = sigm(zf);
                float gg = tanh_(zg), og = sigm(zo);
                float cold = sm->cst[ul * B_ + b];
                float cn = fg * cold + ig * gg;
                sm->cst[ul * B_ + b] = cn;
                float hv = og * tanh_(cn);
                hna[ul] = hv;
                hwr[(u0 + ul) * B_ + b] = hv;
            }
            *(float4 *)&hrow[(size_t)b * U_ + u0] =
                make_float4(hna[0], hna[1], hna[2], hna[3]);
        }
        __threadfence();
        grid_sync();

        // ---- dense head: block bid computes y[bid, :] for this t ----
        sm->hst[tid] = __ldcg(&hrow[(size_t)bid * U_ + tid]);
        __syncthreads();
        {
            int o = tid & (OUT_ - 1), q8 = tid >> 6;   // 8 u-groups of 64
            const float *hq = sm->hst + q8 * 64;
            const float *dwq = sm->dw + (size_t)q8 * 64 * OUT_ + o;
            float a0 = 0.f, a1 = 0.f, a2 = 0.f, a3 = 0.f;
#pragma unroll
            for (int u = 0; u < 64; u += 4) {
                a0 = fmaf(hq[u + 0], dwq[(u + 0) * OUT_], a0);
                a1 = fmaf(hq[u + 1], dwq[(u + 1) * OUT_], a1);
                a2 = fmaf(hq[u + 2], dwq[(u + 2) * OUT_], a2);
                a3 = fmaf(hq[u + 3], dwq[(u + 3) * OUT_], a3);
            }
            sm->ypart[tid] = a0 + a1 + a2 + a3;
        }
        __syncthreads();
        if (tid < OUT_) {
            float y = sm->db[tid];
#pragma unroll
            for (int j = 0; j < 8; j++) y += sm->ypart[j * 64 + tid];
            out[((size_t)bid * T_ + t) * OUT_ + tid] = y;
        }
        p ^= 1;
    }
}

// ------------------------- launch ------------------------------------------
extern "C" void kernel_launch(void *const *d_in, const int *in_sizes, int n_in,
                              void *d_out, int out_size) {
    const float *inputs  = (const float *)d_in[0];   // [128,512,256]
    const float *kernelw = (const float *)d_in[1];   // [320,2048]
    const float *rec     = (const float *)d_in[2];   // [512,2048]
    const float *bias    = (const float *)d_in[3];   // [2048]
    const float *dense_w = (const float *)d_in[4];   // [512,64]
    const float *dense_b = (const float *)d_in[5];   // [64]
    float *out = (float *)d_out;                     // [128,512,64]

    (void)in_sizes; (void)n_in; (void)out_size;

    cudaFuncSetAttribute(lstm_persist,
                         cudaFuncAttributeMaxDynamicSharedMemorySize,
                         (int)sizeof(SmemP));

    prep_reff_kernel<<<U_, 256>>>(kernelw, rec, dense_w);
    prep_bias_kernel<<<G4_ / 256, 256>>>(kernelw, bias, dense_b);
    xproj_kernel<<<dim3(G4_ / 128, T_), 256>>>(inputs, kernelw);
    lstm_persist<<<B_, 512, (int)sizeof(SmemP)>>>(dense_w, dense_b, out);
}

// round 8
// speedup vs baseline: 1.6163x; 1.5347x over previous
#include <cuda_runtime.h>
#include <cuda_bf16.h>
#include <cstdint>

#define B_ 128
#define T_ 512
#define D_ 256
#define U_ 512
#define G4_ 2048
#define OUT_ 64
#define NCTA 128

typedef unsigned long long ull;
typedef unsigned int u32;

// ---- persist smem layout (bytes) ----
#define SM_R     0                      // R resident: 2 terms x 16 rows x 1040B
#define R_TERM   16640
#define SM_AB    33280                  // A bufs: [2 buf][2 term] x (64 rows x 272B)
#define AB_ONE   17408
#define SM_D     102912                 // D: 128 x 18 floats
#define SM_BE    112128                 // 16 floats
#define SM_BRAW  112192                 // 16 floats
#define SM_TOT   112384

// ---- device scratch ----
__device__ float g_xproj[(size_t)T_ * G4_ * B_];          // [t][pcol][b]
__device__ float g_hall[(size_t)B_ * T_ * U_];            // [b][t][u]
__device__ __nv_bfloat16 g_Rhi[(size_t)NCTA * 16 * U_];   // [cta][n][k]
__device__ __nv_bfloat16 g_Rlo[(size_t)NCTA * 16 * U_];
__device__ __nv_bfloat16 g_hKhi[2][U_ * B_];              // [k][m]
__device__ __nv_bfloat16 g_hKlo[2][U_ * B_];
__device__ float g_be2[G4_], g_braw2[G4_];
__device__ unsigned g_cnt = 0, g_gen = 0;

// ---- helpers ----
__device__ __forceinline__ void fma2(ull &a, ull x, ull y) {
    asm("fma.rn.f32x2 %0, %1, %2, %0;" : "+l"(a) : "l"(x), "l"(y));
}
__device__ __forceinline__ ull pack2(float x, float y) {
    ull r; asm("mov.b64 %0, {%1, %2};" : "=l"(r) : "f"(x), "f"(y)); return r;
}
__device__ __forceinline__ float sigm(float x) { return __fdividef(1.f, 1.f + __expf(-x)); }
__device__ __forceinline__ float tanh_(float x) {
    float a = fabsf(x), e = __expf(-2.f * a);
    return copysignf(__fdividef(1.f - e, 1.f + e), x);
}
__device__ __forceinline__ void cpasync16(u32 s, const void *g) {
    asm volatile("cp.async.cg.shared.global [%0], [%1], 16;" :: "r"(s), "l"(g));
}
__device__ __forceinline__ void cpcommit() { asm volatile("cp.async.commit_group;"); }
__device__ __forceinline__ void cpwait0()  { asm volatile("cp.async.wait_group 0;"); }
__device__ __forceinline__ void cpwait1()  { asm volatile("cp.async.wait_group 1;"); }

#define LDSM4(r, a) asm volatile( \
    "ldmatrix.sync.aligned.m8n8.x4.shared.b16 {%0,%1,%2,%3}, [%4];" \
    : "=r"((r)[0]), "=r"((r)[1]), "=r"((r)[2]), "=r"((r)[3]) : "r"(a))
#define LDSM4T(r, a) asm volatile( \
    "ldmatrix.sync.aligned.m8n8.x4.trans.shared.b16 {%0,%1,%2,%3}, [%4];" \
    : "=r"((r)[0]), "=r"((r)[1]), "=r"((r)[2]), "=r"((r)[3]) : "r"(a))
#define MMA(d, a, b) asm volatile( \
    "mma.sync.aligned.m16n8k16.row.col.f32.bf16.bf16.f32 " \
    "{%0,%1,%2,%3}, {%4,%5,%6,%7}, {%8,%9}, {%0,%1,%2,%3};" \
    : "+f"((d)[0]), "+f"((d)[1]), "+f"((d)[2]), "+f"((d)[3]) \
    : "r"((a)[0]), "r"((a)[1]), "r"((a)[2]), "r"((a)[3]), "r"((b)[0]), "r"((b)[1]))

__device__ __forceinline__ void grid_sync() {
    __syncthreads();
    if (threadIdx.x == 0) {
        unsigned gen = *((volatile unsigned *)&g_gen);
        __threadfence();
        unsigned prev = atomicAdd(&g_cnt, 1u);
        if (prev == gridDim.x - 1) {
            atomicExch(&g_cnt, 0u);
            __threadfence();
            atomicAdd(&g_gen, 1u);
        } else {
            while (*((volatile unsigned *)&g_gen) == gen) { }
        }
        __threadfence();
    }
    __syncthreads();
}

// pcol = cta*16 + n;  cta = u>>2, n = (u&3)*4 + gate
__device__ __forceinline__ int perm_col(int col) {
    int u = col & (U_ - 1), gate = col >> 9;
    return (u >> 2) * 16 + (u & 3) * 4 + gate;
}

// ---- prep: R_eff = rec + dw@Kfb, bf16 hi/lo, [cta][n][k] ----
__global__ void prep_reff_kernel(const float *__restrict__ wk,
                                 const float *__restrict__ rec,
                                 const float *__restrict__ dw) {
    int k = blockIdx.x, tid = threadIdx.x;
    __shared__ float dws[OUT_];
    if (tid < OUT_) dws[tid] = dw[k * OUT_ + tid];
    __syncthreads();
    for (int col = tid; col < G4_; col += 256) {
        float acc = rec[k * G4_ + col];
#pragma unroll 16
        for (int j = 0; j < OUT_; j++)
            acc += dws[j] * wk[(size_t)(D_ + j) * G4_ + col];
        size_t dst = (size_t)perm_col(col) * U_ + k;
        __nv_bfloat16 hi = __float2bfloat16(acc);
        g_Rhi[dst] = hi;
        g_Rlo[dst] = __float2bfloat16(acc - __bfloat162float(hi));
    }
}

__global__ void prep_bias_kernel(const float *__restrict__ wk,
                                 const float *__restrict__ bias,
                                 const float *__restrict__ db) {
    int col = blockIdx.x * 256 + threadIdx.x;
    float acc = 0.f;
#pragma unroll 16
    for (int j = 0; j < OUT_; j++)
        acc += db[j] * wk[(size_t)(D_ + j) * G4_ + col];
    int pcol = perm_col(col);
    g_braw2[pcol] = bias[col];
    g_be2[pcol] = bias[col] + acc;
}

// ---- Xproj fp32 GEMM (permuted-col output) ----
#define XKC 16
__global__ void __launch_bounds__(256) xproj_kernel(const float *__restrict__ inp,
                                                    const float *__restrict__ wk) {
    __shared__ float sK[XKC][132];
    __shared__ float sX[XKC][136];
    int tid = threadIdx.x;
    int col0 = blockIdx.x * 128, t = blockIdx.y;
    int tc = tid & 15, tb = tid >> 4;
    int c0 = tc * 8, b0 = tb * 8;
    ull acc[8][4];
#pragma unroll
    for (int c = 0; c < 8; c++)
#pragma unroll
        for (int j = 0; j < 4; j++) acc[c][j] = 0ULL;
    for (int d0 = 0; d0 < D_; d0 += XKC) {
        __syncthreads();
        {
            int ll = tid * 8, dd = ll >> 7, cc = ll & 127;
            const float *src = wk + (size_t)(d0 + dd) * G4_ + col0 + cc;
            *(float4 *)&sK[dd][cc] = *(const float4 *)src;
            *(float4 *)&sK[dd][cc + 4] = *(const float4 *)(src + 4);
        }
        {
            int bb = tid >> 1, f4 = tid & 1;
            const float *src = inp + (size_t)bb * (T_ * D_) + (size_t)t * D_ + d0 + f4 * 8;
            float4 v0 = *(const float4 *)src;
            float4 v1 = *(const float4 *)(src + 4);
            int dbase = f4 * 8;
            sX[dbase + 0][bb] = v0.x; sX[dbase + 1][bb] = v0.y;
            sX[dbase + 2][bb] = v0.z; sX[dbase + 3][bb] = v0.w;
            sX[dbase + 4][bb] = v1.x; sX[dbase + 5][bb] = v1.y;
            sX[dbase + 6][bb] = v1.z; sX[dbase + 7][bb] = v1.w;
        }
        __syncthreads();
#pragma unroll
        for (int dd = 0; dd < XKC; dd++) {
            float4 a0 = *(float4 *)&sK[dd][c0];
            float4 a1 = *(float4 *)&sK[dd][c0 + 4];
            const ull *bp = (const ull *)&sX[dd][b0];
            ull bv0 = bp[0], bv1 = bp[1], bv2 = bp[2], bv3 = bp[3];
            float av[8] = {a0.x, a0.y, a0.z, a0.w, a1.x, a1.y, a1.z, a1.w};
#pragma unroll
            for (int c = 0; c < 8; c++) {
                ull ap = pack2(av[c], av[c]);
                fma2(acc[c][0], ap, bv0); fma2(acc[c][1], ap, bv1);
                fma2(acc[c][2], ap, bv2); fma2(acc[c][3], ap, bv3);
            }
        }
    }
#pragma unroll
    for (int c = 0; c < 8; c++) {
        int pcol = perm_col(col0 + c0 + c);
        size_t base = ((size_t)t * G4_ + pcol) * B_ + b0;
#pragma unroll
        for (int j = 0; j < 4; j++) *(ull *)&g_xproj[base + 2 * j] = acc[c][j];
    }
}

// ---- persistent recurrence on mma.sync bf16 hi/lo ----
__global__ void __launch_bounds__(128, 1) lstm_mma() {
    extern __shared__ char smraw[];
    u32 sb = (u32)__cvta_generic_to_shared(smraw);
    int tid = threadIdx.x, w = tid >> 5, l = tid & 31;
    int cta = blockIdx.x, b = tid;
    float *sD = (float *)(smraw + SM_D);
    float *sbe = (float *)(smraw + SM_BE);
    float *sbr = (float *)(smraw + SM_BRAW);

    if (tid < 16) {
        sbe[tid] = g_be2[cta * 16 + tid];
        sbr[tid] = g_braw2[cta * 16 + tid];
    }
    // stage resident R (hi/lo) into padded smem rows (1040B pitch)
#pragma unroll
    for (int e = 0; e < 2; e++) {
        const char *src = (const char *)(e ? g_Rlo : g_Rhi) + (size_t)cta * 16 * U_ * 2;
#pragma unroll
        for (int i = 0; i < 8; i++) {
            int idx = tid + i * 128;
            int gr = idx >> 6, gc = idx & 63;
            cpasync16(sb + SM_R + e * R_TERM + gr * 1040 + gc * 16, src + idx * 16);
        }
    }
    cpcommit(); cpwait0();
    __syncthreads();

    // lane-derived ldmatrix addressing
    int a_row = ((l & 16) ? 8 : 0) + (l & 7);          // k-row within tile
    int a_mc  = w * 32 + ((l & 8) ? 8 : 0);            // m column
    int b_off = (((l & 16) ? 8 : 0) + (l & 7)) * 1040 + ((l & 8) ? 16 : 0);

    float cst[4] = {0.f, 0.f, 0.f, 0.f};
    int ph = 0;

    for (int t = 0; t < T_; t++) {
        float xpf[16];
#pragma unroll
        for (int n = 0; n < 16; n++)
            xpf[n] = __ldcg(&g_xproj[((size_t)t * G4_ + cta * 16 + n) * B_ + b]);

        float z[16];
        if (t) {
            const char *hhi = (const char *)g_hKhi[ph];
            const char *hlo = (const char *)g_hKlo[ph];
            float acc[2][2][4];
#pragma unroll
            for (int i = 0; i < 2; i++)
#pragma unroll
                for (int nt = 0; nt < 2; nt++)
#pragma unroll
                    for (int j = 0; j < 4; j++) acc[i][nt][j] = 0.f;

            // stage chunk 0 -> buf 0
#pragma unroll
            for (int i = 0; i < 8; i++) {
                int idx = tid + i * 128;
                u32 so = (idx >> 4) * 272 + (idx & 15) * 16;
                cpasync16(sb + SM_AB + 0 * AB_ONE + so, hhi + idx * 16);
                cpasync16(sb + SM_AB + 1 * AB_ONE + so, hlo + idx * 16);
            }
            cpcommit();

            for (int ch = 0; ch < 8; ch++) {
                int buf = ch & 1;
                __syncthreads();   // all warps done reading buf being overwritten
                if (ch < 7) {
                    int nb = buf ^ 1;
                    const char *s1 = hhi + (ch + 1) * 16384;
                    const char *s2 = hlo + (ch + 1) * 16384;
#pragma unroll
                    for (int i = 0; i < 8; i++) {
                        int idx = tid + i * 128;
                        u32 so = (idx >> 4) * 272 + (idx & 15) * 16;
                        cpasync16(sb + SM_AB + (nb * 2 + 0) * AB_ONE + so, s1 + idx * 16);
                        cpasync16(sb + SM_AB + (nb * 2 + 1) * AB_ONE + so, s2 + idx * 16);
                    }
                    cpcommit(); cpwait1();
                } else {
                    cpwait0();
                }
                __syncthreads();

                u32 ahb = sb + SM_AB + (buf * 2 + 0) * AB_ONE;
                u32 alb = sb + SM_AB + (buf * 2 + 1) * AB_ONE;
                u32 bfr[2][4][4];
                // B rows span full K=512; this chunk's k-slice starts at ch*64 (=ch*128 bytes)
#pragma unroll
                for (int e = 0; e < 2; e++)
#pragma unroll
                    for (int kt = 0; kt < 4; kt++)
                        LDSM4(bfr[e][kt],
                              sb + SM_R + e * R_TERM + b_off + (u32)ch * 128 + kt * 32);
#pragma unroll
                for (int i = 0; i < 2; i++) {
#pragma unroll
                    for (int kt = 0; kt < 4; kt++) {
                        u32 ah[4], al[4];
                        u32 aoff = (u32)((kt * 16 + a_row) * 272 + (a_mc + i * 16) * 2);
                        LDSM4T(ah, ahb + aoff);
                        LDSM4T(al, alb + aoff);
#pragma unroll
                        for (int nt = 0; nt < 2; nt++) {
                            MMA(acc[i][nt], ah, &bfr[0][kt][nt * 2]);
                            MMA(acc[i][nt], al, &bfr[0][kt][nt * 2]);
                            MMA(acc[i][nt], ah, &bfr[1][kt][nt * 2]);
                        }
                    }
                }
            }
            // acc -> smem D
#pragma unroll
            for (int i = 0; i < 2; i++)
#pragma unroll
                for (int nt = 0; nt < 2; nt++) {
                    int r = w * 32 + i * 16 + (l >> 2);
                    int cc = nt * 8 + (l & 3) * 2;
                    *(float2 *)&sD[r * 18 + cc] =
                        make_float2(acc[i][nt][0], acc[i][nt][1]);
                    *(float2 *)&sD[(r + 8) * 18 + cc] =
                        make_float2(acc[i][nt][2], acc[i][nt][3]);
                }
            __syncthreads();
#pragma unroll
            for (int n = 0; n < 16; n++) z[n] = sD[b * 18 + n] + xpf[n] + sbe[n];
        } else {
#pragma unroll
            for (int n = 0; n < 16; n++) z[n] = xpf[n] + sbr[n];
        }

        // gates + h
        float hh[4];
#pragma unroll
        for (int ul = 0; ul < 4; ul++) {
            float zi = z[ul * 4 + 0], zf = z[ul * 4 + 1];
            float zg = z[ul * 4 + 2], zo = z[ul * 4 + 3];
            float cn = sigm(zf) * cst[ul] + sigm(zi) * tanh_(zg);
            cst[ul] = cn;
            hh[ul] = sigm(zo) * tanh_(cn);
        }
        *(float4 *)&g_hall[((size_t)b * T_ + t) * U_ + cta * 4] =
            make_float4(hh[0], hh[1], hh[2], hh[3]);
        int nxt = ph ^ 1;
#pragma unroll
        for (int ul = 0; ul < 4; ul++) {
            __nv_bfloat16 hi = __float2bfloat16(hh[ul]);
            __nv_bfloat16 lo = __float2bfloat16(hh[ul] - __bfloat162float(hi));
            g_hKhi[nxt][(cta * 4 + ul) * B_ + b] = hi;
            g_hKlo[nxt][(cta * 4 + ul) * B_ + b] = lo;
        }
        __threadfence();
        grid_sync();
        ph ^= 1;
    }
}

// ---- dense head: Y = H @ dense_w + db ----
__global__ void __launch_bounds__(512) dense_kernel(const float *__restrict__ dw,
                                                    const float *__restrict__ db,
                                                    float *__restrict__ out) {
    __shared__ float sdw[128 * 64];
    __shared__ float sh[16 * 128];
    int tid = threadIdx.x;
    size_t r0 = (size_t)blockIdx.x * 16;
    int o = tid & 63, rr = tid >> 6;
    float a0 = 0.f, a1 = 0.f;
    for (int u0 = 0; u0 < 512; u0 += 128) {
        __syncthreads();
        for (int i = tid; i < 128 * 64; i += 512)
            sdw[i] = dw[(u0 + (i >> 6)) * 64 + (i & 63)];
        for (int i = tid; i < 16 * 128; i += 512)
            sh[i] = g_hall[(r0 + (i >> 7)) * 512 + u0 + (i & 127)];
        __syncthreads();
#pragma unroll 8
        for (int u = 0; u < 128; u++) {
            float wv = sdw[u * 64 + o];
            a0 = fmaf(sh[rr * 128 + u], wv, a0);
            a1 = fmaf(sh[(rr + 8) * 128 + u], wv, a1);
        }
    }
    float bo = db[o];
    out[(r0 + rr) * 64 + o] = a0 + bo;
    out[(r0 + rr + 8) * 64 + o] = a1 + bo;
}

// ---- launch ----
extern "C" void kernel_launch(void *const *d_in, const int *in_sizes, int n_in,
                              void *d_out, int out_size) {
    const float *inputs  = (const float *)d_in[0];
    const float *kernelw = (const float *)d_in[1];
    const float *rec     = (const float *)d_in[2];
    const float *bias    = (const float *)d_in[3];
    const float *dense_w = (const float *)d_in[4];
    const float *dense_b = (const float *)d_in[5];
    float *out = (float *)d_out;
    (void)in_sizes; (void)n_in; (void)out_size;

    cudaFuncSetAttribute(lstm_mma, cudaFuncAttributeMaxDynamicSharedMemorySize, SM_TOT);

    prep_reff_kernel<<<U_, 256>>>(kernelw, rec, dense_w);
    prep_bias_kernel<<<G4_ / 256, 256>>>(kernelw, bias, dense_b);
    xproj_kernel<<<dim3(G4_ / 128, T_), 256>>>(inputs, kernelw);
    lstm_mma<<<NCTA, 128, SM_TOT>>>();
    dense_kernel<<<(B_ * T_) / 16, 512>>>(dense_w, dense_b, out);
}

// round 9
// speedup vs baseline: 1.8744x; 1.1597x over previous
#include <cuda_runtime.h>
#include <cuda_bf16.h>
#include <cstdint>

#define B_ 128
#define T_ 512
#define D_ 256
#define U_ 512
#define G4_ 2048
#define OUT_ 64
#define NCTA 128

typedef unsigned int u32;

// ---- persist smem layout (bytes) — unchanged from R8 ----
#define SM_R     0
#define R_TERM   16640
#define SM_AB    33280
#define AB_ONE   17408
#define SM_D     102912
#define SM_BE    112128
#define SM_BRAW  112192
#define SM_TOT   112384

// ---- xproj_mma smem layout ----
#define XB_TERM  33792            // 64 n-rows x 528B
#define XS_B     0                // 2 terms
#define XA_ONE   17408            // 64 k-rows x 272B
#define XS_A     67584            // [buf][term]
#define XS_D     137216           // 128 x 65 f32
#define XS_TOT   170496

// ---- device scratch ----
__device__ float g_xproj[(size_t)T_ * G4_ * B_];          // [t][pcol][b]
__device__ float g_hall[(size_t)B_ * T_ * U_];            // [b][t][u]
__device__ __nv_bfloat16 g_Rhi[(size_t)NCTA * 16 * U_];   // [cta][n][k]
__device__ __nv_bfloat16 g_Rlo[(size_t)NCTA * 16 * U_];
__device__ __nv_bfloat16 g_hKhi[2][U_ * B_];              // [k][m]
__device__ __nv_bfloat16 g_hKlo[2][U_ * B_];
__device__ __nv_bfloat16 g_xhi[(size_t)T_ * D_ * B_];     // [t][d][b]
__device__ __nv_bfloat16 g_xlo[(size_t)T_ * D_ * B_];
__device__ __nv_bfloat16 g_Khi[(size_t)G4_ * D_];         // [pcol][d]
__device__ __nv_bfloat16 g_Klo[(size_t)G4_ * D_];
__device__ float g_be2[G4_], g_braw2[G4_];
__device__ unsigned g_cnt = 0, g_gen = 0;

// ---- helpers ----
__device__ __forceinline__ float sigm(float x) { return __fdividef(1.f, 1.f + __expf(-x)); }
__device__ __forceinline__ float tanh_(float x) {
    float a = fabsf(x), e = __expf(-2.f * a);
    return copysignf(__fdividef(1.f - e, 1.f + e), x);
}
__device__ __forceinline__ void cpasync16(u32 s, const void *g) {
    asm volatile("cp.async.cg.shared.global [%0], [%1], 16;" :: "r"(s), "l"(g));
}
__device__ __forceinline__ void cpcommit() { asm volatile("cp.async.commit_group;"); }
__device__ __forceinline__ void cpwait0()  { asm volatile("cp.async.wait_group 0;"); }
__device__ __forceinline__ void cpwait1()  { asm volatile("cp.async.wait_group 1;"); }

#define LDSM4(r, a) asm volatile( \
    "ldmatrix.sync.aligned.m8n8.x4.shared.b16 {%0,%1,%2,%3}, [%4];" \
    : "=r"((r)[0]), "=r"((r)[1]), "=r"((r)[2]), "=r"((r)[3]) : "r"(a))
#define LDSM4T(r, a) asm volatile( \
    "ldmatrix.sync.aligned.m8n8.x4.trans.shared.b16 {%0,%1,%2,%3}, [%4];" \
    : "=r"((r)[0]), "=r"((r)[1]), "=r"((r)[2]), "=r"((r)[3]) : "r"(a))
#define MMA(d, a, b) asm volatile( \
    "mma.sync.aligned.m16n8k16.row.col.f32.bf16.bf16.f32 " \
    "{%0,%1,%2,%3}, {%4,%5,%6,%7}, {%8,%9}, {%0,%1,%2,%3};" \
    : "+f"((d)[0]), "+f"((d)[1]), "+f"((d)[2]), "+f"((d)[3]) \
    : "r"((a)[0]), "r"((a)[1]), "r"((a)[2]), "r"((a)[3]), "r"((b)[0]), "r"((b)[1]))

__device__ __forceinline__ void grid_sync() {
    __syncthreads();
    if (threadIdx.x == 0) {
        unsigned gen = *((volatile unsigned *)&g_gen);
        __threadfence();
        unsigned prev = atomicAdd(&g_cnt, 1u);
        if (prev == gridDim.x - 1) {
            atomicExch(&g_cnt, 0u);
            __threadfence();
            atomicAdd(&g_gen, 1u);
        } else {
            while (*((volatile unsigned *)&g_gen) == gen) { }
        }
        __threadfence();
    }
    __syncthreads();
}

// pcol = (u>>2)*16 + (u&3)*4 + gate
__device__ __forceinline__ int perm_col(int col) {
    int u = col & (U_ - 1), gate = col >> 9;
    return (u >> 2) * 16 + (u & 3) * 4 + gate;
}

// ---- prep: R_eff = rec + dw@Kfb, bf16 hi/lo, [cta][n][k] ----
__global__ void prep_reff_kernel(const float *__restrict__ wk,
                                 const float *__restrict__ rec,
                                 const float *__restrict__ dw) {
    int k = blockIdx.x, tid = threadIdx.x;
    __shared__ float dws[OUT_];
    if (tid < OUT_) dws[tid] = dw[k * OUT_ + tid];
    __syncthreads();
    for (int col = tid; col < G4_; col += 256) {
        float acc = rec[k * G4_ + col];
#pragma unroll 16
        for (int j = 0; j < OUT_; j++)
            acc += dws[j] * wk[(size_t)(D_ + j) * G4_ + col];
        size_t dst = (size_t)perm_col(col) * U_ + k;
        __nv_bfloat16 hi = __float2bfloat16(acc);
        g_Rhi[dst] = hi;
        g_Rlo[dst] = __float2bfloat16(acc - __bfloat162float(hi));
    }
}

__global__ void prep_bias_kernel(const float *__restrict__ wk,
                                 const float *__restrict__ bias,
                                 const float *__restrict__ db) {
    int col = blockIdx.x * 256 + threadIdx.x;
    float acc = 0.f;
#pragma unroll 16
    for (int j = 0; j < OUT_; j++)
        acc += db[j] * wk[(size_t)(D_ + j) * G4_ + col];
    int pcol = perm_col(col);
    g_braw2[pcol] = bias[col];
    g_be2[pcol] = bias[col] + acc;
}

// ---- convert kernel weights: wk[d][col] -> g_Khi/Klo [pcol][d] ----
__global__ void cvt_k_kernel(const float *__restrict__ wk) {
    int d = blockIdx.x;
    for (int col = threadIdx.x; col < G4_; col += 256) {
        float v = wk[(size_t)d * G4_ + col];
        __nv_bfloat16 hi = __float2bfloat16(v);
        size_t dst = (size_t)perm_col(col) * D_ + d;
        g_Khi[dst] = hi;
        g_Klo[dst] = __float2bfloat16(v - __bfloat162float(hi));
    }
}

// ---- convert inputs: [b][t][d] f32 -> [t][d][b] bf16 hi/lo ----
__global__ void __launch_bounds__(256) cvt_x_kernel(const float *__restrict__ inp) {
    __shared__ float sm[128 * 65];
    int t = blockIdx.x, d0 = blockIdx.y * 64;
    int tid = threadIdx.x;
#pragma unroll
    for (int i = 0; i < 32; i++) {
        int idx = tid + i * 256;
        int b = idx >> 6, dl = idx & 63;
        sm[b * 65 + dl] = inp[((size_t)b * T_ + t) * D_ + d0 + dl];
    }
    __syncthreads();
#pragma unroll
    for (int i = 0; i < 32; i++) {
        int idx = tid + i * 256;
        int dl = idx >> 7, b = idx & 127;
        float v = sm[b * 65 + dl];
        __nv_bfloat16 hi = __float2bfloat16(v);
        size_t o = ((size_t)t * D_ + d0 + dl) * B_ + b;
        g_xhi[o] = hi;
        g_xlo[o] = __float2bfloat16(v - __bfloat162float(hi));
    }
}

// ---- Xproj on mma.sync bf16 hi/lo ----
// Per CTA: M=128 (b) x N=64 (pcol block) x K=256 (d), two t per CTA.
__global__ void __launch_bounds__(128, 1) xproj_mma() {
    extern __shared__ char smraw[];
    u32 sb = (u32)__cvta_generic_to_shared(smraw);
    float *sD = (float *)(smraw + XS_D);
    int tid = threadIdx.x, w = tid >> 5, l = tid & 31;
    int cb = blockIdx.x;
    int tbase = blockIdx.y * 2;

    // prologue: stage B (weights, both terms) + A chunk0 of t0 (one group)
    {
        const char *kh = (const char *)g_Khi;
        const char *kl = (const char *)g_Klo;
#pragma unroll
        for (int i = 0; i < 16; i++) {
            int idx = tid + i * 128;
            int gr = idx >> 5, gc = idx & 31;
            u32 dsto = (u32)(gr * 528 + gc * 16);
            size_t srco = (((size_t)cb * 64 + gr) << 9) + gc * 16;
            cpasync16(sb + XS_B + dsto, kh + srco);
            cpasync16(sb + XS_B + XB_TERM + dsto, kl + srco);
        }
        const char *xh = (const char *)g_xhi;
        const char *xl = (const char *)g_xlo;
#pragma unroll
        for (int i = 0; i < 8; i++) {
            int idx = tid + i * 128;
            u32 so = (idx >> 4) * 272 + (idx & 15) * 16;
            size_t srco = (((size_t)tbase * D_ + (idx >> 4)) << 8) + (idx & 15) * 16;
            cpasync16(sb + XS_A + 0 * XA_ONE + so, xh + srco);
            cpasync16(sb + XS_A + 1 * XA_ONE + so, xl + srco);
        }
        cpcommit();
    }

    // validated lane mappings (same as lstm_mma)
    int a_row = ((l & 16) ? 8 : 0) + (l & 7);
    int a_mc  = w * 32 + ((l & 8) ? 8 : 0);
    int b_off = (((l & 16) ? 8 : 0) + (l & 7)) * 528 + ((l & 8) ? 16 : 0);

    float acc[2][8][4];
#pragma unroll
    for (int i = 0; i < 2; i++)
#pragma unroll
        for (int n8 = 0; n8 < 8; n8++)
#pragma unroll
            for (int j = 0; j < 4; j++) acc[i][n8][j] = 0.f;

    for (int cc = 0; cc < 8; cc++) {        // 2 t x 4 k-chunks
        int buf = cc & 1;
        __syncthreads();
        if (cc < 7) {
            int nb = buf ^ 1;
            int tn = tbase + ((cc + 1) >> 2);
            int kcn = (cc + 1) & 3;
            const char *xh = (const char *)g_xhi;
            const char *xl = (const char *)g_xlo;
#pragma unroll
            for (int i = 0; i < 8; i++) {
                int idx = tid + i * 128;
                u32 so = (idx >> 4) * 272 + (idx & 15) * 16;
                size_t srco =
                    (((size_t)tn * D_ + kcn * 64 + (idx >> 4)) << 8) + (idx & 15) * 16;
                cpasync16(sb + XS_A + (nb * 2 + 0) * XA_ONE + so, xh + srco);
                cpasync16(sb + XS_A + (nb * 2 + 1) * XA_ONE + so, xl + srco);
            }
            cpcommit(); cpwait1();
        } else {
            cpwait0();
        }
        __syncthreads();

        int kc = cc & 3;
        u32 ahb = sb + XS_A + (buf * 2 + 0) * XA_ONE;
        u32 alb = sb + XS_A + (buf * 2 + 1) * XA_ONE;
#pragma unroll
        for (int kt = 0; kt < 4; kt++) {
            u32 bh[4][4], bl[4][4];
#pragma unroll
            for (int ng = 0; ng < 4; ng++) {
                u32 ba = sb + XS_B + (u32)(ng * (16 * 528)) + b_off
                       + (u32)kc * 128 + kt * 32;
                LDSM4(bh[ng], ba);
                LDSM4(bl[ng], ba + XB_TERM);
            }
#pragma unroll
            for (int i = 0; i < 2; i++) {
                u32 ah[4], al[4];
                u32 aoff = (u32)((kt * 16 + a_row) * 272 + (a_mc + i * 16) * 2);
                LDSM4T(ah, ahb + aoff);
                LDSM4T(al, alb + aoff);
#pragma unroll
                for (int ng = 0; ng < 4; ng++)
#pragma unroll
                    for (int nt = 0; nt < 2; nt++) {
                        MMA(acc[i][ng * 2 + nt], ah, &bh[ng][nt * 2]);
                        MMA(acc[i][ng * 2 + nt], al, &bh[ng][nt * 2]);
                        MMA(acc[i][ng * 2 + nt], ah, &bl[ng][nt * 2]);
                    }
            }
        }

        if (kc == 3) {   // epilogue for this t
            int tcur = tbase + (cc >> 2);
#pragma unroll
            for (int i = 0; i < 2; i++)
#pragma unroll
                for (int n8 = 0; n8 < 8; n8++) {
                    int r = w * 32 + i * 16 + (l >> 2);
                    int ccol = n8 * 8 + (l & 3) * 2;
                    sD[r * 65 + ccol] = acc[i][n8][0];
                    sD[r * 65 + ccol + 1] = acc[i][n8][1];
                    sD[(r + 8) * 65 + ccol] = acc[i][n8][2];
                    sD[(r + 8) * 65 + ccol + 1] = acc[i][n8][3];
                }
            __syncthreads();
            size_t obase = ((size_t)tcur * G4_ + (size_t)cb * 64) * B_;
#pragma unroll
            for (int i = 0; i < 64; i++) {
                int idx = tid + i * 128;
                int n = idx >> 7, b = idx & 127;
                g_xproj[obase + (size_t)n * B_ + b] = sD[b * 65 + n];
            }
            if (cc < 7) {
#pragma unroll
                for (int i = 0; i < 2; i++)
#pragma unroll
                    for (int n8 = 0; n8 < 8; n8++)
#pragma unroll
                        for (int j = 0; j < 4; j++) acc[i][n8][j] = 0.f;
            }
        }
    }
}

// ---- persistent recurrence on mma.sync bf16 hi/lo (unchanged, validated) ----
__global__ void __launch_bounds__(128, 1) lstm_mma() {
    extern __shared__ char smraw[];
    u32 sb = (u32)__cvta_generic_to_shared(smraw);
    int tid = threadIdx.x, w = tid >> 5, l = tid & 31;
    int cta = blockIdx.x, b = tid;
    float *sD = (float *)(smraw + SM_D);
    float *sbe = (float *)(smraw + SM_BE);
    float *sbr = (float *)(smraw + SM_BRAW);

    if (tid < 16) {
        sbe[tid] = g_be2[cta * 16 + tid];
        sbr[tid] = g_braw2[cta * 16 + tid];
    }
#pragma unroll
    for (int e = 0; e < 2; e++) {
        const char *src = (const char *)(e ? g_Rlo : g_Rhi) + (size_t)cta * 16 * U_ * 2;
#pragma unroll
        for (int i = 0; i < 8; i++) {
            int idx = tid + i * 128;
            int gr = idx >> 6, gc = idx & 63;
            cpasync16(sb + SM_R + e * R_TERM + gr * 1040 + gc * 16, src + idx * 16);
        }
    }
    cpcommit(); cpwait0();
    __syncthreads();

    int a_row = ((l & 16) ? 8 : 0) + (l & 7);
    int a_mc  = w * 32 + ((l & 8) ? 8 : 0);
    int b_off = (((l & 16) ? 8 : 0) + (l & 7)) * 1040 + ((l & 8) ? 16 : 0);

    float cst[4] = {0.f, 0.f, 0.f, 0.f};
    int ph = 0;

    for (int t = 0; t < T_; t++) {
        float xpf[16];
#pragma unroll
        for (int n = 0; n < 16; n++)
            xpf[n] = __ldcg(&g_xproj[((size_t)t * G4_ + cta * 16 + n) * B_ + b]);

        float z[16];
        if (t) {
            const char *hhi = (const char *)g_hKhi[ph];
            const char *hlo = (const char *)g_hKlo[ph];
            float acc[2][2][4];
#pragma unroll
            for (int i = 0; i < 2; i++)
#pragma unroll
                for (int nt = 0; nt < 2; nt++)
#pragma unroll
                    for (int j = 0; j < 4; j++) acc[i][nt][j] = 0.f;

#pragma unroll
            for (int i = 0; i < 8; i++) {
                int idx = tid + i * 128;
                u32 so = (idx >> 4) * 272 + (idx & 15) * 16;
                cpasync16(sb + SM_AB + 0 * AB_ONE + so, hhi + idx * 16);
                cpasync16(sb + SM_AB + 1 * AB_ONE + so, hlo + idx * 16);
            }
            cpcommit();

            for (int ch = 0; ch < 8; ch++) {
                int buf = ch & 1;
                __syncthreads();
                if (ch < 7) {
                    int nb = buf ^ 1;
                    const char *s1 = hhi + (ch + 1) * 16384;
                    const char *s2 = hlo + (ch + 1) * 16384;
#pragma unroll
                    for (int i = 0; i < 8; i++) {
                        int idx = tid + i * 128;
                        u32 so = (idx >> 4) * 272 + (idx & 15) * 16;
                        cpasync16(sb + SM_AB + (nb * 2 + 0) * AB_ONE + so, s1 + idx * 16);
                        cpasync16(sb + SM_AB + (nb * 2 + 1) * AB_ONE + so, s2 + idx * 16);
                    }
                    cpcommit(); cpwait1();
                } else {
                    cpwait0();
                }
                __syncthreads();

                u32 ahb = sb + SM_AB + (buf * 2 + 0) * AB_ONE;
                u32 alb = sb + SM_AB + (buf * 2 + 1) * AB_ONE;
                u32 bfr[2][4][4];
#pragma unroll
                for (int e = 0; e < 2; e++)
#pragma unroll
                    for (int kt = 0; kt < 4; kt++)
                        LDSM4(bfr[e][kt],
                              sb + SM_R + e * R_TERM + b_off + (u32)ch * 128 + kt * 32);
#pragma unroll
                for (int i = 0; i < 2; i++) {
#pragma unroll
                    for (int kt = 0; kt < 4; kt++) {
                        u32 ah[4], al[4];
                        u32 aoff = (u32)((kt * 16 + a_row) * 272 + (a_mc + i * 16) * 2);
                        LDSM4T(ah, ahb + aoff);
                        LDSM4T(al, alb + aoff);
#pragma unroll
                        for (int nt = 0; nt < 2; nt++) {
                            MMA(acc[i][nt], ah, &bfr[0][kt][nt * 2]);
                            MMA(acc[i][nt], al, &bfr[0][kt][nt * 2]);
                            MMA(acc[i][nt], ah, &bfr[1][kt][nt * 2]);
                        }
                    }
                }
            }
#pragma unroll
            for (int i = 0; i < 2; i++)
#pragma unroll
                for (int nt = 0; nt < 2; nt++) {
                    int r = w * 32 + i * 16 + (l >> 2);
                    int cc = nt * 8 + (l & 3) * 2;
                    *(float2 *)&sD[r * 18 + cc] =
                        make_float2(acc[i][nt][0], acc[i][nt][1]);
                    *(float2 *)&sD[(r + 8) * 18 + cc] =
                        make_float2(acc[i][nt][2], acc[i][nt][3]);
                }
            __syncthreads();
#pragma unroll
            for (int n = 0; n < 16; n++) z[n] = sD[b * 18 + n] + xpf[n] + sbe[n];
        } else {
#pragma unroll
            for (int n = 0; n < 16; n++) z[n] = xpf[n] + sbr[n];
        }

        float hh[4];
#pragma unroll
        for (int ul = 0; ul < 4; ul++) {
            float zi = z[ul * 4 + 0], zf = z[ul * 4 + 1];
            float zg = z[ul * 4 + 2], zo = z[ul * 4 + 3];
            float cn = sigm(zf) * cst[ul] + sigm(zi) * tanh_(zg);
            cst[ul] = cn;
            hh[ul] = sigm(zo) * tanh_(cn);
        }
        *(float4 *)&g_hall[((size_t)b * T_ + t) * U_ + cta * 4] =
            make_float4(hh[0], hh[1], hh[2], hh[3]);
        int nxt = ph ^ 1;
#pragma unroll
        for (int ul = 0; ul < 4; ul++) {
            __nv_bfloat16 hi = __float2bfloat16(hh[ul]);
            __nv_bfloat16 lo = __float2bfloat16(hh[ul] - __bfloat162float(hi));
            g_hKhi[nxt][(cta * 4 + ul) * B_ + b] = hi;
            g_hKlo[nxt][(cta * 4 + ul) * B_ + b] = lo;
        }
        __threadfence();
        grid_sync();
        ph ^= 1;
    }
}

// ---- dense head: Y = H @ dense_w + db ----
__global__ void __launch_bounds__(512) dense_kernel(const float *__restrict__ dw,
                                                    const float *__restrict__ db,
                                                    float *__restrict__ out) {
    __shared__ float sdw[128 * 64];
    __shared__ float sh[16 * 128];
    int tid = threadIdx.x;
    size_t r0 = (size_t)blockIdx.x * 16;
    int o = tid & 63, rr = tid >> 6;
    float a0 = 0.f, a1 = 0.f;
    for (int u0 = 0; u0 < 512; u0 += 128) {
        __syncthreads();
        for (int i = tid; i < 128 * 64; i += 512)
            sdw[i] = dw[(u0 + (i >> 6)) * 64 + (i & 63)];
        for (int i = tid; i < 16 * 128; i += 512)
            sh[i] = g_hall[(r0 + (i >> 7)) * 512 + u0 + (i & 127)];
        __syncthreads();
#pragma unroll 8
        for (int u = 0; u < 128; u++) {
            float wv = sdw[u * 64 + o];
            a0 = fmaf(sh[rr * 128 + u], wv, a0);
            a1 = fmaf(sh[(rr + 8) * 128 + u], wv, a1);
        }
    }
    float bo = db[o];
    out[(r0 + rr) * 64 + o] = a0 + bo;
    out[(r0 + rr + 8) * 64 + o] = a1 + bo;
}

// ---- launch ----
extern "C" void kernel_launch(void *const *d_in, const int *in_sizes, int n_in,
                              void *d_out, int out_size) {
    const float *inputs  = (const float *)d_in[0];
    const float *kernelw = (const float *)d_in[1];
    const float *rec     = (const float *)d_in[2];
    const float *bias    = (const float *)d_in[3];
    const float *dense_w = (const float *)d_in[4];
    const float *dense_b = (const float *)d_in[5];
    float *out = (float *)d_out;
    (void)in_sizes; (void)n_in; (void)out_size;

    cudaFuncSetAttribute(lstm_mma, cudaFuncAttributeMaxDynamicSharedMemorySize, SM_TOT);
    cudaFuncSetAttribute(xproj_mma, cudaFuncAttributeMaxDynamicSharedMemorySize, XS_TOT);

    cvt_k_kernel<<<D_, 256>>>(kernelw);
    cvt_x_kernel<<<dim3(T_, 4), 256>>>(inputs);
    prep_reff_kernel<<<U_, 256>>>(kernelw, rec, dense_w);
    prep_bias_kernel<<<G4_ / 256, 256>>>(kernelw, bias, dense_b);
    xproj_mma<<<dim3(32, T_ / 2), 128, XS_TOT>>>();
    lstm_mma<<<NCTA, 128, SM_TOT>>>();
    dense_kernel<<<(B_ * T_) / 16, 512>>>(dense_w, dense_b, out);
}